// round 3
// baseline (speedup 1.0000x reference)
#include <cuda_runtime.h>
#include <math.h>

#define N_ROWS 65536
#define D      256
#define K      2048

// ---- scratch (no cudaMalloc allowed) ----
__device__ float g_codeT[K * D];      // codebook transposed [K, D] for coalesced gather
__device__ float g_norms[K];          // ||e_k||^2
__device__ int   g_counts[K];         // code usage counts (int atomics -> deterministic)
__device__ int   g_idx[N_ROWS];       // argmin per row
__device__ float g_partials[2048];    // per-block loss partial sums

// ------------------------------------------------------------------
// k0: transpose codebook [D,K] -> codeT [K,D]; zero counts
// grid (K/32, D/32), block (32, 8)
// ------------------------------------------------------------------
__global__ void transpose_kernel(const float* __restrict__ cb) {
    __shared__ float tile[32][33];
    int k0 = blockIdx.x * 32;
    int d0 = blockIdx.y * 32;
    int x = threadIdx.x, y = threadIdx.y;
    #pragma unroll
    for (int i = 0; i < 32; i += 8)
        tile[y + i][x] = cb[(size_t)(d0 + y + i) * K + k0 + x];
    __syncthreads();
    #pragma unroll
    for (int i = 0; i < 32; i += 8)
        g_codeT[(size_t)(k0 + y + i) * D + d0 + x] = tile[x][y + i];
    if (blockIdx.y == 0 && threadIdx.y == 0)
        g_counts[k0 + x] = 0;
}

// ------------------------------------------------------------------
// k1: per-code squared norms. grid K, block 256 (D threads)
// ------------------------------------------------------------------
__global__ void norms_kernel() {
    __shared__ float sred[256];
    int k = blockIdx.x, t = threadIdx.x;
    float v = g_codeT[(size_t)k * D + t];
    sred[t] = v * v;
    __syncthreads();
    for (int s = 128; s > 0; s >>= 1) {
        if (t < s) sred[t] += sred[t + s];
        __syncthreads();
    }
    if (t == 0) g_norms[k] = sred[0];
}

// ------------------------------------------------------------------
// k2: fused distance-GEMM + running argmin.
// BM=64 rows/block, loops all K codes in BN=64 tiles, BK=16.
// 256 threads, 4x4 register micro-tile per thread.
// dist = ||e||^2 - 2 x.e  (row-constant ||x||^2 dropped; argmin invariant)
// ------------------------------------------------------------------
#define BM 64
#define BN 64
#define BK 16

__global__ __launch_bounds__(256) void argmin_kernel(const float* __restrict__ X,
                                                     const float* __restrict__ CB) {
    __shared__ float As[BK][BM];
    __shared__ float Bs[BK][BN];
    __shared__ float sbest[BM][16];
    __shared__ int   sidx[BM][16];

    int tid = threadIdx.x;
    int row0 = blockIdx.x * BM;
    int ty = tid >> 4, tx = tid & 15;

    float best[4];
    int   bidx[4];
    #pragma unroll
    for (int i = 0; i < 4; i++) { best[i] = 3.4e38f; bidx[i] = 0; }

    // tile-load indices (float4 per thread per tile)
    int at = tid * 4;
    int ar = at >> 4;     // 0..63 row within tile
    int ac = at & 15;     // 0,4,8,12 k within tile
    int br = at >> 6;     // 0..15 k within tile
    int bc = at & 63;     // 0..63 code within tile

    for (int c0 = 0; c0 < K; c0 += BN) {
        float acc[4][4];
        #pragma unroll
        for (int i = 0; i < 4; i++)
            #pragma unroll
            for (int j = 0; j < 4; j++) acc[i][j] = 0.f;

        for (int kk = 0; kk < D; kk += BK) {
            float4 a = *(const float4*)&X[(size_t)(row0 + ar) * D + kk + ac];
            As[ac    ][ar] = a.x;
            As[ac + 1][ar] = a.y;
            As[ac + 2][ar] = a.z;
            As[ac + 3][ar] = a.w;
            float4 b = *(const float4*)&CB[(size_t)(kk + br) * K + c0 + bc];
            *(float4*)&Bs[br][bc] = b;
            __syncthreads();
            #pragma unroll
            for (int k = 0; k < BK; k++) {
                float ra[4], rb[4];
                *(float4*)ra = *(const float4*)&As[k][ty * 4];
                *(float4*)rb = *(const float4*)&Bs[k][tx * 4];
                #pragma unroll
                for (int i = 0; i < 4; i++)
                    #pragma unroll
                    for (int j = 0; j < 4; j++)
                        acc[i][j] = fmaf(ra[i], rb[j], acc[i][j]);
            }
            __syncthreads();
        }
        // epilogue: compare 4 codes x 4 rows (codes ascending -> first-index ties)
        #pragma unroll
        for (int j = 0; j < 4; j++) {
            int code = c0 + tx * 4 + j;
            float nrm = g_norms[code];
            #pragma unroll
            for (int i = 0; i < 4; i++) {
                float dd = fmaf(-2.0f, acc[i][j], nrm);
                if (dd < best[i]) { best[i] = dd; bidx[i] = code; }
            }
        }
    }

    // cross-tx reduction per row (tie -> smaller index, matches jnp.argmin)
    #pragma unroll
    for (int i = 0; i < 4; i++) {
        sbest[ty * 4 + i][tx] = best[i];
        sidx [ty * 4 + i][tx] = bidx[i];
    }
    __syncthreads();
    if (tid < BM) {
        float b = sbest[tid][0];
        int   bi = sidx[tid][0];
        #pragma unroll
        for (int t = 1; t < 16; t++) {
            float v = sbest[tid][t];
            int   vi = sidx[tid][t];
            if (v < b || (v == b && vi < bi)) { b = v; bi = vi; }
        }
        g_idx[row0 + tid] = bi;
        atomicAdd(&g_counts[bi], 1);
    }
}

// ------------------------------------------------------------------
// k3: gather quantized rows (coalesced via codeT), write output,
//     deterministic per-block loss partials. grid 2048 x 256, float4.
// ------------------------------------------------------------------
__global__ __launch_bounds__(256) void quantize_kernel(const float* __restrict__ X,
                                                       float* __restrict__ out) {
    const int total4 = N_ROWS * D / 4;        // 4,194,304
    int stride = gridDim.x * blockDim.x;
    float sum = 0.f;
    for (int i = blockIdx.x * blockDim.x + threadIdx.x; i < total4; i += stride) {
        int row = i >> 6;                      // 64 float4 per row
        int d4  = (i & 63) << 2;
        float4 xv = ((const float4*)X)[i];
        int code = g_idx[row];
        float4 q = *(const float4*)&g_codeT[(size_t)code * D + d4];
        ((float4*)out)[i] = q;
        float dx = xv.x - q.x, dy = xv.y - q.y, dz = xv.z - q.z, dw = xv.w - q.w;
        sum += dx * dx + dy * dy + dz * dz + dw * dw;
    }
    __shared__ float sred[256];
    sred[threadIdx.x] = sum;
    __syncthreads();
    for (int s = 128; s > 0; s >>= 1) {
        if (threadIdx.x < s) sred[threadIdx.x] += sred[threadIdx.x + s];
        __syncthreads();
    }
    if (threadIdx.x == 0) g_partials[blockIdx.x] = sred[0];
}

// ------------------------------------------------------------------
// k4: finalize loss + perplexity (single block, deterministic)
// loss = mean((x-q)^2 + 0.25*(q-x)^2) = 1.25 * sum/(N*D)
// perplexity = exp(-sum p*log(p+1e-10)), p = counts/N
// ------------------------------------------------------------------
__global__ void finalize_kernel(float* __restrict__ out) {
    __shared__ double sd[256];
    int t = threadIdx.x;
    double s = 0.0;
    for (int i = t; i < 2048; i += 256) s += (double)g_partials[i];
    sd[t] = s;
    __syncthreads();
    for (int r = 128; r > 0; r >>= 1) {
        if (t < r) sd[t] += sd[t + r];
        __syncthreads();
    }
    double loss = 1.25 * sd[0] / (double)((long long)N_ROWS * D);
    __syncthreads();

    double h = 0.0;
    for (int i = t; i < K; i += 256) {
        double p = (double)g_counts[i] / (double)N_ROWS;
        h += p * log(p + 1e-10);
    }
    sd[t] = h;
    __syncthreads();
    for (int r = 128; r > 0; r >>= 1) {
        if (t < r) sd[t] += sd[t + r];
        __syncthreads();
    }
    if (t == 0) {
        out[(size_t)N_ROWS * D]     = (float)loss;
        out[(size_t)N_ROWS * D + 1] = (float)exp(-sd[0]);
    }
}

// ------------------------------------------------------------------
extern "C" void kernel_launch(void* const* d_in, const int* in_sizes, int n_in,
                              void* d_out, int out_size) {
    const float* x  = (const float*)d_in[0];   // [64,32,32,256] fp32
    const float* cb = (const float*)d_in[1];   // [256,2048] fp32
    float* out = (float*)d_out;                // [N*D quantized, loss, perplexity]

    transpose_kernel<<<dim3(K / 32, D / 32), dim3(32, 8)>>>(cb);
    norms_kernel<<<K, 256>>>();
    argmin_kernel<<<N_ROWS / BM, 256>>>(x, cb);
    quantize_kernel<<<2048, 256>>>(x, out);
    finalize_kernel<<<1, 256>>>(out);
}

// round 4
// speedup vs baseline: 1.0010x; 1.0010x over previous
#include <cuda_runtime.h>
#include <math.h>

#define N_ROWS 65536
#define D      256
#define K      2048

// ---- scratch (no cudaMalloc allowed) ----
__device__ float g_codeT[K * D];      // codebook transposed [K, D] for coalesced gather
__device__ float g_norms[K];          // ||e_k||^2
__device__ int   g_counts[K];         // code usage counts (int atomics -> deterministic)
__device__ int   g_idx[N_ROWS];       // argmin per row
__device__ float g_partials[2048];    // per-block loss partial sums

// ------------------------------------------------------------------
// k0: transpose codebook [D,K] -> codeT [K,D]; zero counts
// grid (K/32, D/32), block (32, 8)
// ------------------------------------------------------------------
__global__ void transpose_kernel(const float* __restrict__ cb) {
    __shared__ float tile[32][33];
    int k0 = blockIdx.x * 32;
    int d0 = blockIdx.y * 32;
    int x = threadIdx.x, y = threadIdx.y;
    #pragma unroll
    for (int i = 0; i < 32; i += 8)
        tile[y + i][x] = cb[(size_t)(d0 + y + i) * K + k0 + x];
    __syncthreads();
    #pragma unroll
    for (int i = 0; i < 32; i += 8)
        g_codeT[(size_t)(k0 + y + i) * D + d0 + x] = tile[x][y + i];
    if (blockIdx.y == 0 && threadIdx.y == 0)
        g_counts[k0 + x] = 0;
}

// ------------------------------------------------------------------
// k1: per-code squared norms. grid K, block 256 (D threads)
// ------------------------------------------------------------------
__global__ void norms_kernel() {
    __shared__ float sred[256];
    int k = blockIdx.x, t = threadIdx.x;
    float v = g_codeT[(size_t)k * D + t];
    sred[t] = v * v;
    __syncthreads();
    for (int s = 128; s > 0; s >>= 1) {
        if (t < s) sred[t] += sred[t + s];
        __syncthreads();
    }
    if (t == 0) g_norms[k] = sred[0];
}

// ------------------------------------------------------------------
// k2: fused distance-GEMM + running argmin.
// BM=64 rows/block, loops all K codes in BN=64 tiles, BK=16.
// 256 threads, 4x4 register micro-tile per thread.
// dist = ||e||^2 - 2 x.e  (row-constant ||x||^2 dropped; argmin invariant)
// ------------------------------------------------------------------
#define BM 64
#define BN 64
#define BK 16

__global__ __launch_bounds__(256) void argmin_kernel(const float* __restrict__ X,
                                                     const float* __restrict__ CB) {
    __shared__ float As[BK][BM];
    __shared__ float Bs[BK][BN];
    __shared__ float sbest[BM][16];
    __shared__ int   sidx[BM][16];

    int tid = threadIdx.x;
    int row0 = blockIdx.x * BM;
    int ty = tid >> 4, tx = tid & 15;

    float best[4];
    int   bidx[4];
    #pragma unroll
    for (int i = 0; i < 4; i++) { best[i] = 3.4e38f; bidx[i] = 0; }

    // tile-load indices (float4 per thread per tile)
    int at = tid * 4;
    int ar = at >> 4;     // 0..63 row within tile
    int ac = at & 15;     // 0,4,8,12 k within tile
    int br = at >> 6;     // 0..15 k within tile
    int bc = at & 63;     // 0..63 code within tile

    for (int c0 = 0; c0 < K; c0 += BN) {
        float acc[4][4];
        #pragma unroll
        for (int i = 0; i < 4; i++)
            #pragma unroll
            for (int j = 0; j < 4; j++) acc[i][j] = 0.f;

        for (int kk = 0; kk < D; kk += BK) {
            float4 a = *(const float4*)&X[(size_t)(row0 + ar) * D + kk + ac];
            As[ac    ][ar] = a.x;
            As[ac + 1][ar] = a.y;
            As[ac + 2][ar] = a.z;
            As[ac + 3][ar] = a.w;
            float4 b = *(const float4*)&CB[(size_t)(kk + br) * K + c0 + bc];
            *(float4*)&Bs[br][bc] = b;
            __syncthreads();
            #pragma unroll
            for (int k = 0; k < BK; k++) {
                float ra[4], rb[4];
                *(float4*)ra = *(const float4*)&As[k][ty * 4];
                *(float4*)rb = *(const float4*)&Bs[k][tx * 4];
                #pragma unroll
                for (int i = 0; i < 4; i++)
                    #pragma unroll
                    for (int j = 0; j < 4; j++)
                        acc[i][j] = fmaf(ra[i], rb[j], acc[i][j]);
            }
            __syncthreads();
        }
        // epilogue: compare 4 codes x 4 rows (codes ascending -> first-index ties)
        #pragma unroll
        for (int j = 0; j < 4; j++) {
            int code = c0 + tx * 4 + j;
            float nrm = g_norms[code];
            #pragma unroll
            for (int i = 0; i < 4; i++) {
                float dd = fmaf(-2.0f, acc[i][j], nrm);
                if (dd < best[i]) { best[i] = dd; bidx[i] = code; }
            }
        }
    }

    // cross-tx reduction per row (tie -> smaller index, matches jnp.argmin)
    #pragma unroll
    for (int i = 0; i < 4; i++) {
        sbest[ty * 4 + i][tx] = best[i];
        sidx [ty * 4 + i][tx] = bidx[i];
    }
    __syncthreads();
    if (tid < BM) {
        float b = sbest[tid][0];
        int   bi = sidx[tid][0];
        #pragma unroll
        for (int t = 1; t < 16; t++) {
            float v = sbest[tid][t];
            int   vi = sidx[tid][t];
            if (v < b || (v == b && vi < bi)) { b = v; bi = vi; }
        }
        g_idx[row0 + tid] = bi;
        atomicAdd(&g_counts[bi], 1);
    }
}

// ------------------------------------------------------------------
// k3: gather quantized rows (coalesced via codeT), write output,
//     deterministic per-block loss partials. grid 2048 x 256, float4.
// ------------------------------------------------------------------
__global__ __launch_bounds__(256) void quantize_kernel(const float* __restrict__ X,
                                                       float* __restrict__ out) {
    const int total4 = N_ROWS * D / 4;        // 4,194,304
    int stride = gridDim.x * blockDim.x;
    float sum = 0.f;
    for (int i = blockIdx.x * blockDim.x + threadIdx.x; i < total4; i += stride) {
        int row = i >> 6;                      // 64 float4 per row
        int d4  = (i & 63) << 2;
        float4 xv = ((const float4*)X)[i];
        int code = g_idx[row];
        float4 q = *(const float4*)&g_codeT[(size_t)code * D + d4];
        ((float4*)out)[i] = q;
        float dx = xv.x - q.x, dy = xv.y - q.y, dz = xv.z - q.z, dw = xv.w - q.w;
        sum += dx * dx + dy * dy + dz * dz + dw * dw;
    }
    __shared__ float sred[256];
    sred[threadIdx.x] = sum;
    __syncthreads();
    for (int s = 128; s > 0; s >>= 1) {
        if (threadIdx.x < s) sred[threadIdx.x] += sred[threadIdx.x + s];
        __syncthreads();
    }
    if (threadIdx.x == 0) g_partials[blockIdx.x] = sred[0];
}

// ------------------------------------------------------------------
// k4: finalize loss + perplexity (single block, deterministic)
// loss = mean((x-q)^2 + 0.25*(q-x)^2) = 1.25 * sum/(N*D)
// perplexity = exp(-sum p*log(p+1e-10)), p = counts/N
// ------------------------------------------------------------------
__global__ void finalize_kernel(float* __restrict__ out) {
    __shared__ double sd[256];
    int t = threadIdx.x;
    double s = 0.0;
    for (int i = t; i < 2048; i += 256) s += (double)g_partials[i];
    sd[t] = s;
    __syncthreads();
    for (int r = 128; r > 0; r >>= 1) {
        if (t < r) sd[t] += sd[t + r];
        __syncthreads();
    }
    double loss = 1.25 * sd[0] / (double)((long long)N_ROWS * D);
    __syncthreads();

    double h = 0.0;
    for (int i = t; i < K; i += 256) {
        double p = (double)g_counts[i] / (double)N_ROWS;
        h += p * log(p + 1e-10);
    }
    sd[t] = h;
    __syncthreads();
    for (int r = 128; r > 0; r >>= 1) {
        if (t < r) sd[t] += sd[t + r];
        __syncthreads();
    }
    if (t == 0) {
        out[(size_t)N_ROWS * D]     = (float)loss;
        out[(size_t)N_ROWS * D + 1] = (float)exp(-sd[0]);
    }
}

// ------------------------------------------------------------------
extern "C" void kernel_launch(void* const* d_in, const int* in_sizes, int n_in,
                              void* d_out, int out_size) {
    const float* x  = (const float*)d_in[0];   // [64,32,32,256] fp32
    const float* cb = (const float*)d_in[1];   // [256,2048] fp32
    float* out = (float*)d_out;                // [N*D quantized, loss, perplexity]

    transpose_kernel<<<dim3(K / 32, D / 32), dim3(32, 8)>>>(cb);
    norms_kernel<<<K, 256>>>();
    argmin_kernel<<<N_ROWS / BM, 256>>>(x, cb);
    quantize_kernel<<<2048, 256>>>(x, out);
    finalize_kernel<<<1, 256>>>(out);
}

// round 8
// speedup vs baseline: 2.5497x; 2.5473x over previous
#include <cuda_runtime.h>
#include <cuda_fp16.h>
#include <cstdint>
#include <math.h>

#define N_ROWS 65536
#define D      256
#define K      2048

// ---------------- device scratch ----------------
__device__ __align__(16) __half g_xh[N_ROWS][D];   // 64*x hi limb
__device__ __align__(16) __half g_xl[N_ROWS][D];   // 64*x lo limb
__device__ __align__(16) __half g_eh[K][D];        // 64*e hi limb (code-major)
__device__ __align__(16) __half g_el[K][D];        // 64*e lo limb
__device__ float g_codeT[K * D];
__device__ float g_norms[K];
__device__ int   g_counts[K];
__device__ int   g_idx[N_ROWS];
__device__ float g_partials[2048];

__device__ __forceinline__ uint32_t smem_u32(const void* p) {
    uint32_t a;
    asm("{ .reg .u64 t; cvta.to.shared.u64 t, %1; cvt.u32.u64 %0, t; }" : "=r"(a) : "l"(p));
    return a;
}
#define CP_ASYNC16(dst, src) \
    asm volatile("cp.async.cg.shared.global [%0], [%1], 16;" :: "r"(dst), "l"(src))
#define CP_COMMIT() asm volatile("cp.async.commit_group;" ::: "memory")
#define CP_WAIT(n)  asm volatile("cp.async.wait_group %0;" :: "n"(n) : "memory")
#define LDMATRIX4(r, a) \
    asm volatile("ldmatrix.sync.aligned.m8n8.x4.shared.b16 {%0,%1,%2,%3}, [%4];" \
        : "=r"((r)[0]), "=r"((r)[1]), "=r"((r)[2]), "=r"((r)[3]) : "r"(a))
#define MMA16816(c, a, b) \
    asm volatile("mma.sync.aligned.m16n8k16.row.col.f32.f16.f16.f32 " \
        "{%0,%1,%2,%3}, {%4,%5,%6,%7}, {%8,%9}, {%0,%1,%2,%3};" \
        : "+f"((c)[0]), "+f"((c)[1]), "+f"((c)[2]), "+f"((c)[3]) \
        : "r"((a)[0]), "r"((a)[1]), "r"((a)[2]), "r"((a)[3]), "r"((b)[0]), "r"((b)[1]))

// ---------------- prep kernels ----------------
__global__ void transpose_kernel(const float* __restrict__ cb) {
    __shared__ float tile[32][33];
    int k0 = blockIdx.x * 32, d0 = blockIdx.y * 32, x = threadIdx.x, y = threadIdx.y;
    #pragma unroll
    for (int i = 0; i < 32; i += 8) tile[y + i][x] = cb[(size_t)(d0 + y + i) * K + k0 + x];
    __syncthreads();
    #pragma unroll
    for (int i = 0; i < 32; i += 8) {
        int k = k0 + y + i, d = d0 + x;
        float v = tile[x][y + i];
        g_codeT[(size_t)k * D + d] = v;
        float vs = v * 64.0f;
        __half h = __float2half(vs);
        g_eh[k][d] = h;
        g_el[k][d] = __float2half(vs - __half2float(h));
    }
    if (blockIdx.y == 0 && threadIdx.y == 0) g_counts[k0 + x] = 0;
}

__global__ void norms_kernel() {
    __shared__ float s[256];
    int k = blockIdx.x, t = threadIdx.x;
    float v = g_codeT[(size_t)k * D + t];
    s[t] = v * v;
    __syncthreads();
    for (int r = 128; r > 0; r >>= 1) { if (t < r) s[t] += s[t + r]; __syncthreads(); }
    if (t == 0) g_norms[k] = s[0];
}

__global__ __launch_bounds__(256) void split_x_kernel(const float* __restrict__ X) {
    int i = blockIdx.x * 256 + threadIdx.x;       // 2,097,152 threads, 8 floats each
    int row = i >> 5, d0 = (i & 31) << 3;
    const float4* src = (const float4*)(X + (size_t)row * D + d0);
    float4 v0 = src[0], v1 = src[1];
    float vs[8] = {v0.x, v0.y, v0.z, v0.w, v1.x, v1.y, v1.z, v1.w};
    __align__(16) __half ph[8], pl[8];
    #pragma unroll
    for (int j = 0; j < 8; j++) {
        float v = vs[j] * 64.0f;
        __half h = __float2half(v);
        ph[j] = h;
        pl[j] = __float2half(v - __half2float(h));
    }
    *(uint4*)&g_xh[row][d0] = *(uint4*)ph;
    *(uint4*)&g_xl[row][d0] = *(uint4*)pl;
}

// ---------------- main: HMMA distance GEMM + fused argmin ----------------
// grid 512, block 256 (8 warps: mwarp=wid&3 -> 32 rows, nwarp=wid>>2 -> 64 cols)
// K-concat GEMM: k 0..255 xh*eh, 256..511 xh*el, 512..767 xl*eh (all *64 scale)
#define SSTAGE 32768   // A 16KB + B 16KB per stage
__global__ __launch_bounds__(256, 1) void argmin_mma_kernel() {
    extern __shared__ char smem[];
    uint32_t sb = smem_u32(smem);
    __shared__ float sB[128];
    __shared__ int   sI[128];

    int tid = threadIdx.x, l = tid & 31, wid = tid >> 5;
    int mwarp = wid & 3, nwarp = wid >> 2;
    int row0 = blockIdx.x * 128;

    // per-thread cp.async source row/col (4 iters each for A and B)
    int lrow[4], lcolb[4];
    #pragma unroll
    for (int j = 0; j < 4; j++) {
        int lin = j * 256 + tid;          // 0..1023 -> 128 rows x 8 x 16B
        lrow[j] = lin >> 3;
        lcolb[j] = (lin & 7) * 16;
    }

    float best[2][2];
    int   bidx[2][2];
    #pragma unroll
    for (int a = 0; a < 2; a++)
        #pragma unroll
        for (int b = 0; b < 2; b++) { best[a][b] = 3.4e38f; bidx[a][b] = 0; }

    for (int ct = 0; ct < 16; ct++) {
        int c0 = ct * 128;
        float acc[2][8][4];
        #pragma unroll
        for (int mf = 0; mf < 2; mf++)
            #pragma unroll
            for (int nf = 0; nf < 8; nf++)
                #pragma unroll
                for (int q = 0; q < 4; q++) acc[mf][nf][q] = 0.f;

        // prefetch chunk 0 into stage 0
        #pragma unroll
        for (int j = 0; j < 4; j++) {
            const char* sa = (const char*)&g_xh[row0 + lrow[j]][0] + lcolb[j];
            int off = lrow[j] * 128 + lcolb[j];
            CP_ASYNC16(sb + (off ^ ((off >> 3) & 0x70)), sa);
            const char* sbp = (const char*)&g_eh[c0 + lrow[j]][0] + lcolb[j];
            CP_ASYNC16(sb + 16384 + (off ^ ((off >> 3) & 0x70)), sbp);
        }
        CP_COMMIT();

        for (int kc = 0; kc < 12; kc++) {
            if (kc < 11) {
                int kn = kc + 1;
                int koff = (kn & 3) * 64;                        // halves
                const __half* Asrc = (kn < 8) ? &g_xh[0][0] : &g_xl[0][0];
                const __half* Bsrc = (kn >= 4 && kn < 8) ? &g_el[0][0] : &g_eh[0][0];
                uint32_t st = sb + ((kn & 1) ? SSTAGE : 0);
                #pragma unroll
                for (int j = 0; j < 4; j++) {
                    int off = lrow[j] * 128 + lcolb[j];
                    int sw = off ^ ((off >> 3) & 0x70);
                    const char* sa = (const char*)(Asrc + (size_t)(row0 + lrow[j]) * D + koff) + lcolb[j];
                    CP_ASYNC16(st + sw, sa);
                    const char* sp = (const char*)(Bsrc + (size_t)(c0 + lrow[j]) * D + koff) + lcolb[j];
                    CP_ASYNC16(st + 16384 + sw, sp);
                }
                CP_COMMIT();
                CP_WAIT(1);
            } else {
                CP_WAIT(0);
            }
            __syncthreads();

            uint32_t aBase = sb + ((kc & 1) ? SSTAGE : 0);
            uint32_t bBase = aBase + 16384;
            #pragma unroll
            for (int ks = 0; ks < 4; ks++) {
                uint32_t afr[2][4];
                #pragma unroll
                for (int mf = 0; mf < 2; mf++) {
                    int row = mwarp * 32 + mf * 16 + (l & 15);
                    int colb = ks * 32 + ((l >> 4) << 4);
                    int off = row * 128 + colb;
                    LDMATRIX4(afr[mf], aBase + (off ^ ((off >> 3) & 0x70)));
                }
                uint32_t bfr[8][2];
                #pragma unroll
                for (int np = 0; np < 4; np++) {
                    int code = nwarp * 64 + np * 16 + (l & 7) + ((l & 16) ? 8 : 0);
                    int colb = ks * 32 + ((l & 8) ? 16 : 0);
                    int off = code * 128 + colb;
                    uint32_t r[4];
                    LDMATRIX4(r, bBase + (off ^ ((off >> 3) & 0x70)));
                    bfr[np * 2][0] = r[0]; bfr[np * 2][1] = r[1];
                    bfr[np * 2 + 1][0] = r[2]; bfr[np * 2 + 1][1] = r[3];
                }
                #pragma unroll
                for (int mf = 0; mf < 2; mf++)
                    #pragma unroll
                    for (int nf = 0; nf < 8; nf++)
                        MMA16816(acc[mf][nf], afr[mf], bfr[nf]);
            }
            __syncthreads();
        }

        // epilogue: dist = 4096*||e||^2 - 2*sim_scaled ; cols ascending
        #pragma unroll
        for (int nf = 0; nf < 8; nf++) {
            int n0 = c0 + nwarp * 64 + nf * 8 + 2 * (l & 3);
            float nr0 = __ldg(&g_norms[n0]) * 4096.0f;
            float nr1 = __ldg(&g_norms[n0 + 1]) * 4096.0f;
            #pragma unroll
            for (int mf = 0; mf < 2; mf++) {
                float d00 = fmaf(-2.0f, acc[mf][nf][0], nr0);
                float d01 = fmaf(-2.0f, acc[mf][nf][1], nr1);
                float d10 = fmaf(-2.0f, acc[mf][nf][2], nr0);
                float d11 = fmaf(-2.0f, acc[mf][nf][3], nr1);
                if (d00 < best[mf][0]) { best[mf][0] = d00; bidx[mf][0] = n0; }
                if (d01 < best[mf][0]) { best[mf][0] = d01; bidx[mf][0] = n0 + 1; }
                if (d10 < best[mf][1]) { best[mf][1] = d10; bidx[mf][1] = n0; }
                if (d11 < best[mf][1]) { best[mf][1] = d11; bidx[mf][1] = n0 + 1; }
            }
        }
    }

    // lane merge (lanes with same l>>2 share rows; l&3 spans cols)
    #pragma unroll
    for (int mf = 0; mf < 2; mf++)
        #pragma unroll
        for (int rh = 0; rh < 2; rh++) {
            float bv = best[mf][rh]; int bi = bidx[mf][rh];
            #pragma unroll
            for (int dlt = 1; dlt <= 2; dlt <<= 1) {
                float ov = __shfl_xor_sync(0xFFFFFFFFu, bv, dlt);
                int   oi = __shfl_xor_sync(0xFFFFFFFFu, bi, dlt);
                if (ov < bv || (ov == bv && oi < bi)) { bv = ov; bi = oi; }
            }
            best[mf][rh] = bv; bidx[mf][rh] = bi;
        }
    __syncthreads();
    if (nwarp == 0 && (l & 3) == 0) {
        #pragma unroll
        for (int mf = 0; mf < 2; mf++)
            #pragma unroll
            for (int rh = 0; rh < 2; rh++) {
                int rl = mwarp * 32 + mf * 16 + rh * 8 + (l >> 2);
                sB[rl] = best[mf][rh]; sI[rl] = bidx[mf][rh];
            }
    }
    __syncthreads();
    if (nwarp == 1 && (l & 3) == 0) {
        #pragma unroll
        for (int mf = 0; mf < 2; mf++)
            #pragma unroll
            for (int rh = 0; rh < 2; rh++) {
                int rl = mwarp * 32 + mf * 16 + rh * 8 + (l >> 2);
                float bv = best[mf][rh]; int bi = bidx[mf][rh];
                float ov = sB[rl]; int oi = sI[rl];
                if (ov < bv || (ov == bv && oi < bi)) { bv = ov; bi = oi; }
                g_idx[row0 + rl] = bi;
                atomicAdd(&g_counts[bi], 1);
            }
    }
}

// ---------------- epilogue kernels ----------------
__global__ __launch_bounds__(256) void quantize_kernel(const float* __restrict__ X,
                                                       float* __restrict__ out) {
    const int total4 = N_ROWS * D / 4;
    int stride = gridDim.x * blockDim.x;
    float sum = 0.f;
    for (int i = blockIdx.x * blockDim.x + threadIdx.x; i < total4; i += stride) {
        int row = i >> 6, d4 = (i & 63) << 2;
        float4 xv = ((const float4*)X)[i];
        float4 q = *(const float4*)&g_codeT[(size_t)g_idx[row] * D + d4];
        ((float4*)out)[i] = q;
        float dx = xv.x - q.x, dy = xv.y - q.y, dz = xv.z - q.z, dw = xv.w - q.w;
        sum += dx * dx + dy * dy + dz * dz + dw * dw;
    }
    __shared__ float s[256];
    s[threadIdx.x] = sum;
    __syncthreads();
    for (int r = 128; r > 0; r >>= 1) { if (threadIdx.x < r) s[threadIdx.x] += s[threadIdx.x + r]; __syncthreads(); }
    if (threadIdx.x == 0) g_partials[blockIdx.x] = s[0];
}

__global__ void finalize_kernel(float* __restrict__ out) {
    __shared__ double sd[256];
    int t = threadIdx.x;
    double s = 0.0;
    for (int i = t; i < 2048; i += 256) s += (double)g_partials[i];
    sd[t] = s;
    __syncthreads();
    for (int r = 128; r > 0; r >>= 1) { if (t < r) sd[t] += sd[t + r]; __syncthreads(); }
    double loss = 1.25 * sd[0] / (double)((long long)N_ROWS * D);
    __syncthreads();
    double h = 0.0;
    for (int i = t; i < K; i += 256) {
        double p = (double)g_counts[i] / (double)N_ROWS;
        h += p * log(p + 1e-10);
    }
    sd[t] = h;
    __syncthreads();
    for (int r = 128; r > 0; r >>= 1) { if (t < r) sd[t] += sd[t + r]; __syncthreads(); }
    if (t == 0) {
        out[(size_t)N_ROWS * D]     = (float)loss;
        out[(size_t)N_ROWS * D + 1] = (float)exp(-sd[0]);
    }
}

// ------------------------------------------------------------------
extern "C" void kernel_launch(void* const* d_in, const int* in_sizes, int n_in,
                              void* d_out, int out_size) {
    const float* x  = (const float*)d_in[0];
    const float* cb = (const float*)d_in[1];
    float* out = (float*)d_out;

    // idempotent, capture-legal; called unconditionally (no static guards)
    cudaFuncSetAttribute(argmin_mma_kernel,
                         cudaFuncAttributeMaxDynamicSharedMemorySize, 2 * SSTAGE);

    transpose_kernel<<<dim3(K / 32, D / 32), dim3(32, 8)>>>(cb);
    norms_kernel<<<K, 256>>>();
    split_x_kernel<<<N_ROWS * D / 8 / 256, 256>>>(x);
    argmin_mma_kernel<<<N_ROWS / 128, 256, 2 * SSTAGE>>>();
    quantize_kernel<<<2048, 256>>>(x, out);
    finalize_kernel<<<1, 256>>>(out);
}